// round 3
// baseline (speedup 1.0000x reference)
#include <cuda_runtime.h>

#define Bn 8
#define Cn 64
#define Hn 64
#define Wn 64

typedef unsigned long long ull;

__device__ __forceinline__ ull pack2(float lo, float hi) {
    ull r; asm("mov.b64 %0, {%1, %2};" : "=l"(r) : "f"(lo), "f"(hi)); return r;
}
__device__ __forceinline__ void unpack2(ull v, float& lo, float& hi) {
    asm("mov.b64 {%0, %1}, %2;" : "=f"(lo), "=f"(hi) : "l"(v));
}
__device__ __forceinline__ ull ffma2(ull a, ull b, ull c) {
    ull d; asm("fma.rn.f32x2 %0, %1, %2, %3;" : "=l"(d) : "l"(a), "l"(b), "l"(c)); return d;
}

__device__ float g_f1[Bn*64*Hn*Wn];    // conv1 out [b][c][h][w]
__device__ float g_f2t[Bn*32*Wn*Hn];   // conv2 out transposed [b][c][w][h]

// ---------------------------------------------------------------------------
// conv1: 3x3 64->64, zero pad, bias+PReLU. Block = 2 h-rows, 128 threads.
// Thread: 8 co x 8 w. ci chunked by 4. All pairs via ld.shared.v2.u64.
// ---------------------------------------------------------------------------
__global__ __launch_bounds__(128, 4) void conv1_kernel(
    const float* __restrict__ x, const float* __restrict__ wgt,
    const float* __restrict__ bias, const float* __restrict__ alpha)
{
    const int h0 = blockIdx.x * 2, b = blockIdx.y;
    const int tid = threadIdx.x;
    const int row = tid >> 6;
    const int t   = tid & 63;
    const int wb  = (t & 7) * 8;
    const int cob = (t >> 3) * 8;

    __shared__ __align__(16) float sA[4][4][64];   // [ci][r][w] even-aligned
    __shared__ __align__(16) float sB[4][4][68];   // [ci][r][2p..2p+1]=(x[2p-1],x[2p])
    __shared__ __align__(16) float sW[4][9][128];  // [ci][k][2*co] dup pairs

    // hoisted fill decodes
    const int fi_ci = tid >> 5, fi_r = (tid >> 3) & 3, fi_seg = tid & 7;
    const int hh = h0 - 1 + fi_r;
    const bool inh = (hh >= 0) && (hh < Hn);
    const int fw_co = tid >> 1, fw_ci0 = (tid & 1) * 2;

    ull acc[8][4];
#pragma unroll
    for (int i = 0; i < 8; i++)
#pragma unroll
        for (int j = 0; j < 4; j++) acc[i][j] = 0ull;

    for (int cb = 0; cb < 16; cb++) {
        {   // input fill: (ci, r, 8-col segment)
            const float* src = x + (((b*64 + cb*4 + fi_ci)*Hn + hh)*Wn) + fi_seg*8;
            float4 g0 = make_float4(0.f,0.f,0.f,0.f), g1 = g0;
            float xm1 = 0.f;
            if (inh) {
                g0 = *(const float4*)src;
                g1 = *(const float4*)(src + 4);
                if (fi_seg > 0) xm1 = src[-1];
            }
            *(float4*)&sA[fi_ci][fi_r][fi_seg*8]     = g0;
            *(float4*)&sA[fi_ci][fi_r][fi_seg*8 + 4] = g1;
            *(float4*)&sB[fi_ci][fi_r][fi_seg*8]     = make_float4(xm1, g0.x, g0.y, g0.z);
            *(float4*)&sB[fi_ci][fi_r][fi_seg*8 + 4] = make_float4(g0.w, g1.x, g1.y, g1.z);
            if (fi_seg == 7) { sB[fi_ci][fi_r][64] = g1.w; sB[fi_ci][fi_r][65] = 0.f; }
        }
        {   // weight fill: thread = (co, 2-ci half)
            const float* wp = wgt + (fw_co*64 + cb*4 + fw_ci0)*9;
#pragma unroll
            for (int cc = 0; cc < 2; cc++)
#pragma unroll
                for (int k = 0; k < 9; k++) {
                    float v = wp[cc*9 + k];
                    *(ull*)&sW[fw_ci0 + cc][k][fw_co*2] = pack2(v, v);
                }
        }
        __syncthreads();

#pragma unroll 2
        for (int ci = 0; ci < 4; ci++) {
#pragma unroll
            for (int ky = 0; ky < 3; ky++) {
                const int r = row + ky;
                ulonglong2 a01 = *(const ulonglong2*)&sA[ci][r][wb];
                ulonglong2 a23 = *(const ulonglong2*)&sA[ci][r][wb + 4];
                ulonglong2 b01 = *(const ulonglong2*)&sB[ci][r][wb];
                ulonglong2 b23 = *(const ulonglong2*)&sB[ci][r][wb + 4];
                ull b4 = *(const ull*)&sB[ci][r][wb + 8];
                ull Ap[4] = {a01.x, a01.y, a23.x, a23.y};
                ull Bp[5] = {b01.x, b01.y, b23.x, b23.y, b4};
#pragma unroll
                for (int kx = 0; kx < 3; kx++) {
                    const ull* wr = (const ull*)&sW[ci][ky*3 + kx][0] + cob;
                    ulonglong2 w01 = *(const ulonglong2*)(wr);
                    ulonglong2 w23 = *(const ulonglong2*)(wr + 2);
                    ulonglong2 w45 = *(const ulonglong2*)(wr + 4);
                    ulonglong2 w67 = *(const ulonglong2*)(wr + 6);
                    ull wc[8] = {w01.x, w01.y, w23.x, w23.y, w45.x, w45.y, w67.x, w67.y};
#pragma unroll
                    for (int cl = 0; cl < 8; cl++)
#pragma unroll
                        for (int j = 0; j < 4; j++) {
                            ull px = (kx == 0) ? Bp[j] : (kx == 1) ? Ap[j] : Bp[j + 1];
                            acc[cl][j] = ffma2(wc[cl], px, acc[cl][j]);
                        }
                }
            }
        }
        __syncthreads();
    }

    const int h = h0 + row;
    float4 bq0 = *(const float4*)&bias[cob],  bq1 = *(const float4*)&bias[cob + 4];
    float4 aq0 = *(const float4*)&alpha[cob], aq1 = *(const float4*)&alpha[cob + 4];
    float bvs[8] = {bq0.x,bq0.y,bq0.z,bq0.w,bq1.x,bq1.y,bq1.z,bq1.w};
    float avs[8] = {aq0.x,aq0.y,aq0.z,aq0.w,aq1.x,aq1.y,aq1.z,aq1.w};
#pragma unroll
    for (int cl = 0; cl < 8; cl++) {
        float o[8];
#pragma unroll
        for (int j = 0; j < 4; j++) unpack2(acc[cl][j], o[2*j], o[2*j+1]);
#pragma unroll
        for (int e = 0; e < 8; e++) {
            float v = o[e] + bvs[cl];
            o[e] = v > 0.f ? v : avs[cl]*v;
        }
        float* op = &g_f1[((b*64 + cob + cl)*Hn + h)*Wn + wb];
        *(float4*)op       = make_float4(o[0], o[1], o[2], o[3]);
        *(float4*)(op + 4) = make_float4(o[4], o[5], o[6], o[7]);
    }
}

// ---------------------------------------------------------------------------
// conv2: 3x3 64->32, zero pad, bias+PReLU, transposed output [b][c][w][h].
// Thread: 4 co x 8 w. Same pair machinery.
// ---------------------------------------------------------------------------
__global__ __launch_bounds__(128, 5) void conv2_kernel(
    const float* __restrict__ wgt, const float* __restrict__ bias,
    const float* __restrict__ alpha)
{
    const int h0 = blockIdx.x * 2, b = blockIdx.y;
    const int tid = threadIdx.x;
    const int row = tid >> 6;
    const int t   = tid & 63;
    const int wb  = (t & 7) * 8;
    const int cob = (t >> 3) * 4;

    __shared__ __align__(16) float sA[4][4][64];
    __shared__ __align__(16) float sB[4][4][68];
    __shared__ __align__(16) float sW[4][9][64];

    const int fi_ci = tid >> 5, fi_r = (tid >> 3) & 3, fi_seg = tid & 7;
    const int hh = h0 - 1 + fi_r;
    const bool inh = (hh >= 0) && (hh < Hn);
    const int fw_co = tid >> 2, fw_ci = tid & 3;

    ull acc[4][4];
#pragma unroll
    for (int i = 0; i < 4; i++)
#pragma unroll
        for (int j = 0; j < 4; j++) acc[i][j] = 0ull;

    for (int cb = 0; cb < 16; cb++) {
        {
            const float* src = g_f1 + (((b*64 + cb*4 + fi_ci)*Hn + hh)*Wn) + fi_seg*8;
            float4 g0 = make_float4(0.f,0.f,0.f,0.f), g1 = g0;
            float xm1 = 0.f;
            if (inh) {
                g0 = *(const float4*)src;
                g1 = *(const float4*)(src + 4);
                if (fi_seg > 0) xm1 = src[-1];
            }
            *(float4*)&sA[fi_ci][fi_r][fi_seg*8]     = g0;
            *(float4*)&sA[fi_ci][fi_r][fi_seg*8 + 4] = g1;
            *(float4*)&sB[fi_ci][fi_r][fi_seg*8]     = make_float4(xm1, g0.x, g0.y, g0.z);
            *(float4*)&sB[fi_ci][fi_r][fi_seg*8 + 4] = make_float4(g0.w, g1.x, g1.y, g1.z);
            if (fi_seg == 7) { sB[fi_ci][fi_r][64] = g1.w; sB[fi_ci][fi_r][65] = 0.f; }
        }
        {
            const float* wp = wgt + (fw_co*64 + cb*4 + fw_ci)*9;
#pragma unroll
            for (int k = 0; k < 9; k++) {
                float v = wp[k];
                *(ull*)&sW[fw_ci][k][fw_co*2] = pack2(v, v);
            }
        }
        __syncthreads();

#pragma unroll 2
        for (int ci = 0; ci < 4; ci++) {
#pragma unroll
            for (int ky = 0; ky < 3; ky++) {
                const int r = row + ky;
                ulonglong2 a01 = *(const ulonglong2*)&sA[ci][r][wb];
                ulonglong2 a23 = *(const ulonglong2*)&sA[ci][r][wb + 4];
                ulonglong2 b01 = *(const ulonglong2*)&sB[ci][r][wb];
                ulonglong2 b23 = *(const ulonglong2*)&sB[ci][r][wb + 4];
                ull b4 = *(const ull*)&sB[ci][r][wb + 8];
                ull Ap[4] = {a01.x, a01.y, a23.x, a23.y};
                ull Bp[5] = {b01.x, b01.y, b23.x, b23.y, b4};
#pragma unroll
                for (int kx = 0; kx < 3; kx++) {
                    const ull* wr = (const ull*)&sW[ci][ky*3 + kx][0] + cob;
                    ulonglong2 w01 = *(const ulonglong2*)(wr);
                    ulonglong2 w23 = *(const ulonglong2*)(wr + 2);
                    ull wc[4] = {w01.x, w01.y, w23.x, w23.y};
#pragma unroll
                    for (int cl = 0; cl < 4; cl++)
#pragma unroll
                        for (int j = 0; j < 4; j++) {
                            ull px = (kx == 0) ? Bp[j] : (kx == 1) ? Ap[j] : Bp[j + 1];
                            acc[cl][j] = ffma2(wc[cl], px, acc[cl][j]);
                        }
                }
            }
        }
        __syncthreads();
    }

    const int h = h0 + row;
    float4 bq = *(const float4*)&bias[cob];
    float4 aq = *(const float4*)&alpha[cob];
    float bvs[4] = {bq.x,bq.y,bq.z,bq.w};
    float avs[4] = {aq.x,aq.y,aq.z,aq.w};
#pragma unroll
    for (int cl = 0; cl < 4; cl++) {
        const int co = cob + cl;
#pragma unroll
        for (int j = 0; j < 4; j++) {
            float lo, hi; unpack2(acc[cl][j], lo, hi);
            lo += bvs[cl]; hi += bvs[cl];
            lo = lo > 0.f ? lo : avs[cl]*lo;
            hi = hi > 0.f ? hi : avs[cl]*hi;
            g_f2t[((b*32 + co)*Wn + wb + 2*j    )*Hn + h] = lo;
            g_f2t[((b*32 + co)*Wn + wb + 2*j + 1)*Hn + h] = hi;
        }
    }
}

// ---------------------------------------------------------------------------
// Fused: 1x1 conv (K=32) + softmax(9) + upsample. 128 threads.
// Thread = (c_l, pq, pg): 9 logits x 8 h-pixels. out[b][c][2w+q][2h+p].
// ---------------------------------------------------------------------------
__global__ __launch_bounds__(128, 3) void fused_kernel(
    const float* __restrict__ xlow, const float* __restrict__ kw,
    const float* __restrict__ kb, float* __restrict__ out)
{
    const int cchunk = blockIdx.x;
    const int w      = blockIdx.y;
    const int b      = blockIdx.z;
    const int tid = threadIdx.x;
    const int pg  = tid & 7;
    const int pq  = (tid >> 3) & 3;
    const int c_l = tid >> 5;
    const int cg  = c_l*4 + pq;

    __shared__ __align__(16) ull   sW8[16][32][8];   // [cg][ci][k<8] dup pairs
    __shared__ ull                 sW1[16][32];      // k==8
    __shared__ __align__(16) float sf2[32*64];       // [ci][h]
    __shared__ __align__(16) float sx[4][3][68];     // [c_l][dx][h+1] edge-clamped
    __shared__ float sbias[144];

    for (int idx = tid; idx < 32*64; idx += 128)
        sf2[idx] = g_f2t[((b*32 + (idx >> 6))*Wn + w)*Hn + (idx & 63)];
    {   // weights: thread = (cg2, 4-ci group)
        const int cg2 = tid >> 3, cig = tid & 7;
        const int rowb = (cg2 >> 2)*36 + (cg2 & 3);
#pragma unroll
        for (int k = 0; k < 9; k++) {
            float4 wv = *(const float4*)&kw[(cchunk*144 + rowb + k*4)*32 + cig*4];
            float vs[4] = {wv.x, wv.y, wv.z, wv.w};
#pragma unroll
            for (int cc = 0; cc < 4; cc++) {
                ull d = pack2(vs[cc], vs[cc]);
                if (k < 8) sW8[cg2][cig*4 + cc][k] = d;
                else       sW1[cg2][cig*4 + cc]    = d;
            }
        }
    }
    for (int idx = tid; idx < 144; idx += 128) sbias[idx] = kb[cchunk*144 + idx];
    for (int idx = tid; idx < 4*3*66; idx += 128) {
        int cl = idx / 198;
        int dx = (idx % 198) / 66;
        int hh = idx % 66;
        int hr = min(max(hh - 1, 0), Hn - 1);
        int wc = min(max(w + dx - 1, 0), Wn - 1);
        sx[cl][dx][hh] = xlow[((b*Cn + cchunk*4 + cl)*Hn + hr)*Wn + wc];
    }
    __syncthreads();

    ull m[9][4];
#pragma unroll
    for (int k = 0; k < 9; k++)
#pragma unroll
        for (int j = 0; j < 4; j++) m[k][j] = 0ull;

#pragma unroll 4
    for (int ci = 0; ci < 32; ci++) {
        ulonglong2 p01 = *(const ulonglong2*)&sf2[ci*64 + pg*8];
        ulonglong2 p23 = *(const ulonglong2*)&sf2[ci*64 + pg*8 + 4];
        ull P[4] = {p01.x, p01.y, p23.x, p23.y};
        const ull* wr = &sW8[cg][ci][0];
        ulonglong2 w01 = *(const ulonglong2*)(wr);
        ulonglong2 w23 = *(const ulonglong2*)(wr + 2);
        ulonglong2 w45 = *(const ulonglong2*)(wr + 4);
        ulonglong2 w67 = *(const ulonglong2*)(wr + 6);
        ull W[9] = {w01.x, w01.y, w23.x, w23.y, w45.x, w45.y, w67.x, w67.y, sW1[cg][ci]};
#pragma unroll
        for (int k = 0; k < 9; k++)
#pragma unroll
            for (int j = 0; j < 4; j++) m[k][j] = ffma2(W[k], P[j], m[k][j]);
    }

    const int rowb = c_l*36 + pq;
    float b9[9];
#pragma unroll
    for (int k = 0; k < 9; k++) b9[k] = sbias[rowb + k*4];

    // neighbor rows for all 8 pixels: nbd[dx][0..9]
    float nbd[3][10];
#pragma unroll
    for (int dx = 0; dx < 3; dx++) {
        float4 q0 = *(const float4*)&sx[c_l][dx][pg*8];
        float4 q1 = *(const float4*)&sx[c_l][dx][pg*8 + 4];
        float2 q2 = *(const float2*)&sx[c_l][dx][pg*8 + 8];
        nbd[dx][0]=q0.x; nbd[dx][1]=q0.y; nbd[dx][2]=q0.z; nbd[dx][3]=q0.w;
        nbd[dx][4]=q1.x; nbd[dx][5]=q1.y; nbd[dx][6]=q1.z; nbd[dx][7]=q1.w;
        nbd[dx][8]=q2.x; nbd[dx][9]=q2.y;
    }

    const int c = cchunk*4 + c_l;
    const int p = pq >> 1, q = pq & 1;
    float* orow = &out[((b*Cn + c)*128 + (2*w + q))*128 + p];

#pragma unroll
    for (int jj = 0; jj < 4; jj++) {
        float lo[9], hi[9];
#pragma unroll
        for (int k = 0; k < 9; k++) unpack2(m[k][jj], lo[k], hi[k]);
#pragma unroll
        for (int e = 0; e < 2; e++) {
            const int j = 2*jj + e;
            const float* lv = e ? hi : lo;
            float se = 0.f, sv = 0.f;
#pragma unroll
            for (int k = 0; k < 9; k++) {
                float ex = __expf(lv[k] + b9[k]);   // logits tiny: no max-sub needed
                se += ex;
                sv = fmaf(ex, nbd[k % 3][j + k / 3], sv);
            }
            orow[2*(pg*8 + j)] = sv * __fdividef(1.f, se);
        }
    }
}

extern "C" void kernel_launch(void* const* d_in, const int* in_sizes, int n_in,
                              void* d_out, int out_size)
{
    const float* x_low = (const float*)d_in[0];
    const float* ctx   = (const float*)d_in[1];
    const float* c1_w  = (const float*)d_in[2];
    const float* c1_b  = (const float*)d_in[3];
    const float* p1_a  = (const float*)d_in[4];
    const float* c2_w  = (const float*)d_in[5];
    const float* c2_b  = (const float*)d_in[6];
    const float* p2_a  = (const float*)d_in[7];
    const float* kp_w  = (const float*)d_in[8];
    const float* kp_b  = (const float*)d_in[9];
    float* out = (float*)d_out;

    conv1_kernel<<<dim3(Hn/2, Bn), 128>>>(ctx, c1_w, c1_b, p1_a);
    conv2_kernel<<<dim3(Hn/2, Bn), 128>>>(c2_w, c2_b, p2_a);
    fused_kernel<<<dim3(16, Wn, Bn), 128>>>(x_low, kp_w, kp_b, out);
}

// round 4
// speedup vs baseline: 1.0752x; 1.0752x over previous
#include <cuda_runtime.h>

#define Bn 8
#define Cn 64
#define Hn 64
#define Wn 64

typedef unsigned long long ull;

__device__ __forceinline__ ull pack2(float lo, float hi) {
    ull r; asm("mov.b64 %0, {%1, %2};" : "=l"(r) : "f"(lo), "f"(hi)); return r;
}
__device__ __forceinline__ void unpack2(ull v, float& lo, float& hi) {
    asm("mov.b64 {%0, %1}, %2;" : "=f"(lo), "=f"(hi) : "l"(v));
}
__device__ __forceinline__ ull ffma2(ull a, ull b, ull c) {
    ull d; asm("fma.rn.f32x2 %0, %1, %2, %3;" : "=l"(d) : "l"(a), "l"(b), "l"(c)); return d;
}

__device__ float g_f1[Bn*64*Hn*Wn];    // conv1 out [b][c][h][w]
__device__ float g_f2t[Bn*32*Wn*Hn];   // conv2 out transposed [b][c][w][h]

// ---------------------------------------------------------------------------
// conv1: 3x3 64->64, zero pad, bias+PReLU. 1 h-row per 128-thread block.
// Thread: 4 co x 8 w. ci chunked by 4. grid (64, 8) = 512 blocks.
// ---------------------------------------------------------------------------
__global__ __launch_bounds__(128, 5) void conv1_kernel(
    const float* __restrict__ x, const float* __restrict__ wgt,
    const float* __restrict__ bias, const float* __restrict__ alpha)
{
    const int h = blockIdx.x, b = blockIdx.y;
    const int tid = threadIdx.x;
    const int wb  = (tid & 7) * 8;     // 8 pixels
    const int cob = (tid >> 3) * 4;    // 4 channels (16 groups)

    __shared__ __align__(16) float sA[4][3][64];   // [ci][ky][w] even-aligned
    __shared__ __align__(16) float sB[4][3][68];   // [ci][ky][2p..2p+1]=(x[2p-1],x[2p])
    __shared__ __align__(16) ull   sW[4][9][64];   // [ci][k][co] dup pairs

    // fill decodes (hoisted)
    const int fi_ci = tid >> 5, fi_r = (tid >> 3) & 3, fi_seg = tid & 7; // fi_r<3 active
    const int hh = h - 1 + fi_r;
    const bool inh = (fi_r < 3) && (hh >= 0) && (hh < Hn);
    const int fw_co = tid >> 1, fw_ci0 = (tid & 1) * 2;

    ull acc[4][4];
#pragma unroll
    for (int i = 0; i < 4; i++)
#pragma unroll
        for (int j = 0; j < 4; j++) acc[i][j] = 0ull;

    for (int cb = 0; cb < 16; cb++) {
        if (fi_r < 3) {   // input fill: (ci, ky row, 8-col segment)
            float4 g0 = make_float4(0.f,0.f,0.f,0.f), g1 = g0;
            float xm1 = 0.f;
            if (inh) {
                const float* src = x + (((b*64 + cb*4 + fi_ci)*Hn + hh)*Wn) + fi_seg*8;
                g0 = *(const float4*)src;
                g1 = *(const float4*)(src + 4);
                if (fi_seg > 0) xm1 = src[-1];
            }
            *(float4*)&sA[fi_ci][fi_r][fi_seg*8]     = g0;
            *(float4*)&sA[fi_ci][fi_r][fi_seg*8 + 4] = g1;
            *(float4*)&sB[fi_ci][fi_r][fi_seg*8]     = make_float4(xm1, g0.x, g0.y, g0.z);
            *(float4*)&sB[fi_ci][fi_r][fi_seg*8 + 4] = make_float4(g0.w, g1.x, g1.y, g1.z);
            if (fi_seg == 7) { sB[fi_ci][fi_r][64] = g1.w; sB[fi_ci][fi_r][65] = 0.f; }
        }
        {   // weight fill: thread = (co, 2-ci half)
            const float* wp = wgt + (fw_co*64 + cb*4 + fw_ci0)*9;
#pragma unroll
            for (int cc = 0; cc < 2; cc++)
#pragma unroll
                for (int k = 0; k < 9; k++) {
                    float v = wp[cc*9 + k];
                    sW[fw_ci0 + cc][k][fw_co] = pack2(v, v);
                }
        }
        __syncthreads();

#pragma unroll
        for (int ci = 0; ci < 4; ci++) {
#pragma unroll
            for (int ky = 0; ky < 3; ky++) {
                ulonglong2 a01 = *(const ulonglong2*)&sA[ci][ky][wb];
                ulonglong2 a23 = *(const ulonglong2*)&sA[ci][ky][wb + 4];
                ulonglong2 b01 = *(const ulonglong2*)&sB[ci][ky][wb];
                ulonglong2 b23 = *(const ulonglong2*)&sB[ci][ky][wb + 4];
                ull b4 = *(const ull*)&sB[ci][ky][wb + 8];
                ull Ap[4] = {a01.x, a01.y, a23.x, a23.y};
                ull Bp[5] = {b01.x, b01.y, b23.x, b23.y, b4};
#pragma unroll
                for (int kx = 0; kx < 3; kx++) {
                    const ull* wr = &sW[ci][ky*3 + kx][cob];
                    ulonglong2 w01 = *(const ulonglong2*)(wr);
                    ulonglong2 w23 = *(const ulonglong2*)(wr + 2);
                    ull wc[4] = {w01.x, w01.y, w23.x, w23.y};
#pragma unroll
                    for (int cl = 0; cl < 4; cl++)
#pragma unroll
                        for (int j = 0; j < 4; j++) {
                            ull px = (kx == 0) ? Bp[j] : (kx == 1) ? Ap[j] : Bp[j + 1];
                            acc[cl][j] = ffma2(wc[cl], px, acc[cl][j]);
                        }
                }
            }
        }
        __syncthreads();
    }

    float4 bq = *(const float4*)&bias[cob];
    float4 aq = *(const float4*)&alpha[cob];
    float bvs[4] = {bq.x,bq.y,bq.z,bq.w};
    float avs[4] = {aq.x,aq.y,aq.z,aq.w};
#pragma unroll
    for (int cl = 0; cl < 4; cl++) {
        float o[8];
#pragma unroll
        for (int j = 0; j < 4; j++) unpack2(acc[cl][j], o[2*j], o[2*j+1]);
#pragma unroll
        for (int e = 0; e < 8; e++) {
            float v = o[e] + bvs[cl];
            o[e] = v > 0.f ? v : avs[cl]*v;
        }
        float* op = &g_f1[((b*64 + cob + cl)*Hn + h)*Wn + wb];
        *(float4*)op       = make_float4(o[0], o[1], o[2], o[3]);
        *(float4*)(op + 4) = make_float4(o[4], o[5], o[6], o[7]);
    }
}

// ---------------------------------------------------------------------------
// conv2: 3x3 64->32, zero pad, bias+PReLU, transposed out [b][c][w][h].
// 1 h-row per 128-thread block. Thread: 4 co x 4 w. grid (64, 8).
// ---------------------------------------------------------------------------
__global__ __launch_bounds__(128, 6) void conv2_kernel(
    const float* __restrict__ wgt, const float* __restrict__ bias,
    const float* __restrict__ alpha)
{
    const int h = blockIdx.x, b = blockIdx.y;
    const int tid = threadIdx.x;
    const int wb  = (tid & 15) * 4;    // 4 pixels (16 groups)
    const int cob = (tid >> 4) * 4;    // 4 channels (8 groups)

    __shared__ __align__(16) float sA[4][3][64];
    __shared__ __align__(16) float sB[4][3][68];
    __shared__ __align__(16) ull   sW[4][9][32];

    const int fi_ci = tid >> 5, fi_r = (tid >> 3) & 3, fi_seg = tid & 7;
    const int hh = h - 1 + fi_r;
    const bool inh = (fi_r < 3) && (hh >= 0) && (hh < Hn);
    const int fw_co = tid >> 2, fw_ci = tid & 3;

    ull acc[4][2];
#pragma unroll
    for (int i = 0; i < 4; i++)
#pragma unroll
        for (int j = 0; j < 2; j++) acc[i][j] = 0ull;

    for (int cb = 0; cb < 16; cb++) {
        if (fi_r < 3) {
            float4 g0 = make_float4(0.f,0.f,0.f,0.f), g1 = g0;
            float xm1 = 0.f;
            if (inh) {
                const float* src = g_f1 + (((b*64 + cb*4 + fi_ci)*Hn + hh)*Wn) + fi_seg*8;
                g0 = *(const float4*)src;
                g1 = *(const float4*)(src + 4);
                if (fi_seg > 0) xm1 = src[-1];
            }
            *(float4*)&sA[fi_ci][fi_r][fi_seg*8]     = g0;
            *(float4*)&sA[fi_ci][fi_r][fi_seg*8 + 4] = g1;
            *(float4*)&sB[fi_ci][fi_r][fi_seg*8]     = make_float4(xm1, g0.x, g0.y, g0.z);
            *(float4*)&sB[fi_ci][fi_r][fi_seg*8 + 4] = make_float4(g0.w, g1.x, g1.y, g1.z);
            if (fi_seg == 7) { sB[fi_ci][fi_r][64] = g1.w; sB[fi_ci][fi_r][65] = 0.f; }
        }
        {
            const float* wp = wgt + (fw_co*64 + cb*4 + fw_ci)*9;
#pragma unroll
            for (int k = 0; k < 9; k++) {
                float v = wp[k];
                sW[fw_ci][k][fw_co] = pack2(v, v);
            }
        }
        __syncthreads();

#pragma unroll
        for (int ci = 0; ci < 4; ci++) {
#pragma unroll
            for (int ky = 0; ky < 3; ky++) {
                ulonglong2 a01 = *(const ulonglong2*)&sA[ci][ky][wb];
                ulonglong2 b01 = *(const ulonglong2*)&sB[ci][ky][wb];
                ull b2 = *(const ull*)&sB[ci][ky][wb + 4];
                ull Ap[2] = {a01.x, a01.y};
                ull Bp[3] = {b01.x, b01.y, b2};
#pragma unroll
                for (int kx = 0; kx < 3; kx++) {
                    const ull* wr = &sW[ci][ky*3 + kx][cob];
                    ulonglong2 w01 = *(const ulonglong2*)(wr);
                    ulonglong2 w23 = *(const ulonglong2*)(wr + 2);
                    ull wc[4] = {w01.x, w01.y, w23.x, w23.y};
#pragma unroll
                    for (int cl = 0; cl < 4; cl++)
#pragma unroll
                        for (int j = 0; j < 2; j++) {
                            ull px = (kx == 0) ? Bp[j] : (kx == 1) ? Ap[j] : Bp[j + 1];
                            acc[cl][j] = ffma2(wc[cl], px, acc[cl][j]);
                        }
                }
            }
        }
        __syncthreads();
    }

    float4 bq = *(const float4*)&bias[cob];
    float4 aq = *(const float4*)&alpha[cob];
    float bvs[4] = {bq.x,bq.y,bq.z,bq.w};
    float avs[4] = {aq.x,aq.y,aq.z,aq.w};
#pragma unroll
    for (int cl = 0; cl < 4; cl++) {
        const int co = cob + cl;
#pragma unroll
        for (int j = 0; j < 2; j++) {
            float lo, hi; unpack2(acc[cl][j], lo, hi);
            lo += bvs[cl]; hi += bvs[cl];
            lo = lo > 0.f ? lo : avs[cl]*lo;
            hi = hi > 0.f ? hi : avs[cl]*hi;
            g_f2t[((b*32 + co)*Wn + wb + 2*j    )*Hn + h] = lo;
            g_f2t[((b*32 + co)*Wn + wb + 2*j + 1)*Hn + h] = hi;
        }
    }
}

// ---------------------------------------------------------------------------
// Fused: 1x1 conv (K=32) + softmax(9) + upsample. 128 threads, 8192 blocks.
// Plain f32 weights in smem (pack-on-fly). Thread = (c_l, pq, pg): 9x8px.
// out[b][c][2w+q][2h+p] per reference transpose(0,1,5,3,4,2).
// ---------------------------------------------------------------------------
__global__ __launch_bounds__(128, 4) void fused_kernel(
    const float* __restrict__ xlow, const float* __restrict__ kw,
    const float* __restrict__ kb, float* __restrict__ out)
{
    const int cchunk = blockIdx.x;
    const int w      = blockIdx.y;
    const int b      = blockIdx.z;
    const int tid = threadIdx.x;
    const int pg  = tid & 7;
    const int pq  = (tid >> 3) & 3;
    const int c_l = tid >> 5;

    __shared__ float swt[144*33];                  // plain f32 weights, pad 33
    __shared__ __align__(16) float sf2[32*64];     // [ci][h]
    __shared__ __align__(16) float sx[4][3][68];   // edge-clamped x_low patch
    __shared__ float sbias[144];

    for (int idx = tid; idx < 32*64; idx += 128)
        sf2[idx] = g_f2t[((b*32 + (idx >> 6))*Wn + w)*Hn + (idx & 63)];
    for (int idx = tid; idx < 144*32; idx += 128) {
        int r = idx >> 5, ci = idx & 31;
        swt[r*33 + ci] = kw[(cchunk*144 + r)*32 + ci];
    }
    for (int idx = tid; idx < 144; idx += 128) sbias[idx] = kb[cchunk*144 + idx];
    for (int idx = tid; idx < 4*3*66; idx += 128) {
        int cl = idx / 198;
        int dx = (idx % 198) / 66;
        int hh = idx % 66;
        int hr = min(max(hh - 1, 0), Hn - 1);
        int wc = min(max(w + dx - 1, 0), Wn - 1);
        sx[cl][dx][hh] = xlow[((b*Cn + cl + cchunk*4)*Hn + hr)*Wn + wc];
    }
    __syncthreads();

    ull m[9][4];
#pragma unroll
    for (int k = 0; k < 9; k++)
#pragma unroll
        for (int j = 0; j < 4; j++) m[k][j] = 0ull;

    const int rowb = c_l*36 + pq;
    const float* wtb = &swt[rowb*33];

#pragma unroll 4
    for (int ci = 0; ci < 32; ci++) {
        ulonglong2 p01 = *(const ulonglong2*)&sf2[ci*64 + pg*8];
        ulonglong2 p23 = *(const ulonglong2*)&sf2[ci*64 + pg*8 + 4];
        ull P[4] = {p01.x, p01.y, p23.x, p23.y};
        ull W[9];
#pragma unroll
        for (int k = 0; k < 9; k++) {
            float v = wtb[k*4*33 + ci];
            W[k] = pack2(v, v);
        }
#pragma unroll
        for (int k = 0; k < 9; k++)
#pragma unroll
            for (int j = 0; j < 4; j++) m[k][j] = ffma2(W[k], P[j], m[k][j]);
    }

    float b9[9];
#pragma unroll
    for (int k = 0; k < 9; k++) b9[k] = sbias[rowb + k*4];

    float nbd[3][10];
#pragma unroll
    for (int dx = 0; dx < 3; dx++) {
        float4 q0 = *(const float4*)&sx[c_l][dx][pg*8];
        float4 q1 = *(const float4*)&sx[c_l][dx][pg*8 + 4];
        float2 q2 = *(const float2*)&sx[c_l][dx][pg*8 + 8];
        nbd[dx][0]=q0.x; nbd[dx][1]=q0.y; nbd[dx][2]=q0.z; nbd[dx][3]=q0.w;
        nbd[dx][4]=q1.x; nbd[dx][5]=q1.y; nbd[dx][6]=q1.z; nbd[dx][7]=q1.w;
        nbd[dx][8]=q2.x; nbd[dx][9]=q2.y;
    }

    const int c = cchunk*4 + c_l;
    const int p = pq >> 1, q = pq & 1;
    float* orow = &out[((b*Cn + c)*128 + (2*w + q))*128 + p];

#pragma unroll
    for (int jj = 0; jj < 4; jj++) {
        float lo[9], hi[9];
#pragma unroll
        for (int k = 0; k < 9; k++) unpack2(m[k][jj], lo[k], hi[k]);
#pragma unroll
        for (int e = 0; e < 2; e++) {
            const int j = 2*jj + e;
            const float* lv = e ? hi : lo;
            float se = 0.f, sv = 0.f;
#pragma unroll
            for (int k = 0; k < 9; k++) {
                float ex = __expf(lv[k] + b9[k]);   // logits tiny: no max-sub needed
                se += ex;
                sv = fmaf(ex, nbd[k % 3][j + k / 3], sv);
            }
            orow[2*(pg*8 + j)] = sv * __fdividef(1.f, se);
        }
    }
}

extern "C" void kernel_launch(void* const* d_in, const int* in_sizes, int n_in,
                              void* d_out, int out_size)
{
    const float* x_low = (const float*)d_in[0];
    const float* ctx   = (const float*)d_in[1];
    const float* c1_w  = (const float*)d_in[2];
    const float* c1_b  = (const float*)d_in[3];
    const float* p1_a  = (const float*)d_in[4];
    const float* c2_w  = (const float*)d_in[5];
    const float* c2_b  = (const float*)d_in[6];
    const float* p2_a  = (const float*)d_in[7];
    const float* kp_w  = (const float*)d_in[8];
    const float* kp_b  = (const float*)d_in[9];
    float* out = (float*)d_out;

    conv1_kernel<<<dim3(Hn, Bn), 128>>>(ctx, c1_w, c1_b, p1_a);
    conv2_kernel<<<dim3(Hn, Bn), 128>>>(c2_w, c2_b, p2_a);
    fused_kernel<<<dim3(16, Wn, Bn), 128>>>(x_low, kp_w, kp_b, out);
}